// round 14
// baseline (speedup 1.0000x reference)
#include <cuda_runtime.h>
#include <cuda_fp16.h>
#include <cstdint>

#define D_IN 128
#define D_H  256
#define KCL  16
#define TM   128
#define NT   128

// ---- smem layout (32-bit word offsets) ----
#define SM_XS  0                        // xs  [128][68] fp16x2 kpairs
#define SM_W1  8704                     // W1h [256][68] fp16x2 (n-major)
#define SM_W2  (8704 + 17408)           // W2h [16][132] fp16x2      26112
#define SM_B1  (SM_W2 + 2112)           // b1 fp32 [256]             28224
#define SM_B2  (SM_B1 + 256)            // b2 fp32 [16]              28480
#define SM_TOT (SM_B2 + 16)             // 28496 words
#define SMEM_BYTES (SM_TOT * 4)         // 113984 B -> 2 CTAs/SM

#define CB_CAP 131072
__device__ uint4 g_Cu8[CB_CAP];         // u8 fixed-point copy of C, 16 B/row
__device__ float g_edge_sum;
__device__ int   g_done;

__device__ __forceinline__ uint32_t pack_h2(float a, float b) {
    __half2 h = __floats2half2_rn(a, b);
    return *(uint32_t*)&h;
}

__device__ __forceinline__ void mma_f16(float* d, const uint32_t* a, const uint32_t* b) {
    asm volatile(
        "mma.sync.aligned.m16n8k16.row.col.f32.f16.f16.f32 "
        "{%0,%1,%2,%3}, {%4,%5,%6,%7}, {%8,%9}, {%0,%1,%2,%3};"
        : "+f"(d[0]), "+f"(d[1]), "+f"(d[2]), "+f"(d[3])
        : "r"(a[0]), "r"(a[1]), "r"(a[2]), "r"(a[3]), "r"(b[0]), "r"(b[1]));
}

// Persistent fused MLP+softmax. Warp tile = 32 rows x 256 cols in 4 quarters;
// layer-2 A operand is a register rename of layer-1 accumulators (no staging,
// no cross-warp reduction, 2 barriers/tile).
__global__ __launch_bounds__(NT, 2)
void fused_mlp_softmax(const float* __restrict__ x,
                       const float* __restrict__ W1,
                       const float* __restrict__ b1,
                       const float* __restrict__ W2,
                       const float* __restrict__ b2,
                       float* __restrict__ C,
                       int N, int ntiles, int write_u8)
{
    extern __shared__ float smf[];
    uint32_t* smw = (uint32_t*)smf;
    uint32_t* xs  = smw + SM_XS;
    uint32_t* W1s = smw + SM_W1;
    uint32_t* W2s = smw + SM_W2;
    float* b1s = smf + SM_B1;
    float* b2s = smf + SM_B2;

    const int tid = threadIdx.x;
    const int wid = tid >> 5, lane = tid & 31;
    const int g = lane >> 2, tg = lane & 3;
    const int rb = wid * 32;            // warp's 32-row slab

    // ---- once: pack W1/W2 fp32 -> fp16x2 smem, stage biases ----
    for (int i = tid; i < 256 * 64; i += NT) {
        int n = i & 255, kp = i >> 8;
        W1s[n * 68 + kp] = pack_h2(W1[(2 * kp) * D_H + n], W1[(2 * kp + 1) * D_H + n]);
    }
    for (int i = tid; i < 16 * 128; i += NT) {
        int kk = i & 15, kp = i >> 4;
        W2s[kk * 132 + kp] = pack_h2(W2[(2 * kp) * KCL + kk], W2[(2 * kp + 1) * KCL + kk]);
    }
    for (int i = tid; i < D_H; i += NT) b1s[i] = b1[i];
    if (tid < KCL) b2s[tid] = b2[tid];

    const float4* xv = (const float4*)x;
    const int xrw = tid >> 5;           // warp stages rows 32*wid..+31
    const int xc4 = tid & 31;

    for (int tile = blockIdx.x; tile < ntiles; tile += gridDim.x) {
        const int row_base = tile * TM;

        // ---- phase 0: x tile -> fp16x2 smem (each warp its 32 rows) ----
        #pragma unroll 4
        for (int k = 0; k < 32; k++) {
            int r = xrw * 32 + k;
            int gr = row_base + r;
            float4 v = make_float4(0.f, 0.f, 0.f, 0.f);
            if (gr < N) v = __ldg(&xv[(size_t)gr * 32 + xc4]);
            uint2 u;
            u.x = pack_h2(v.x, v.y);
            u.y = pack_h2(v.z, v.w);
            *(uint2*)&xs[r * 68 + 2 * xc4] = u;
        }
        __syncthreads();

        // ---- cache all A-fragments for this warp's 32 rows (64 regs) ----
        uint32_t aall[8][2][4];
        #pragma unroll
        for (int ks = 0; ks < 8; ks++) {
            const int kp0 = 8 * ks + tg;
            #pragma unroll
            for (int mf = 0; mf < 2; mf++) {
                int r0 = rb + mf * 16 + g;
                aall[ks][mf][0] = xs[r0 * 68 + kp0];
                aall[ks][mf][1] = xs[(r0 + 8) * 68 + kp0];
                aall[ks][mf][2] = xs[r0 * 68 + kp0 + 4];
                aall[ks][mf][3] = xs[(r0 + 8) * 68 + kp0 + 4];
            }
        }
        __syncthreads();   // xs reads done; safe for next tile's STS later

        // ---- layer-2 accumulators (rows rb.., cols 0..15) ----
        float s2[2][2][4];
        #pragma unroll
        for (int mf = 0; mf < 2; mf++)
            #pragma unroll
            for (int nf2 = 0; nf2 < 2; nf2++)
                #pragma unroll
                for (int q = 0; q < 4; q++) s2[mf][nf2][q] = 0.f;

        // ---- 4 quarters of 64 h-columns each ----
        #pragma unroll 1
        for (int q0 = 0; q0 < 4; q0++) {
            const int qbase = 64 * q0;

            float acc[2][8][4];
            #pragma unroll
            for (int mf = 0; mf < 2; mf++)
                #pragma unroll
                for (int nf = 0; nf < 8; nf++)
                    #pragma unroll
                    for (int q = 0; q < 4; q++) acc[mf][nf][q] = 0.f;

            // layer 1 over this quarter
            #pragma unroll
            for (int ks = 0; ks < 8; ks++) {
                const int kp0 = 8 * ks + tg;
                uint32_t b[8][2];
                #pragma unroll
                for (int nf = 0; nf < 8; nf++) {
                    int n = qbase + nf * 8 + g;
                    b[nf][0] = W1s[n * 68 + kp0];
                    b[nf][1] = W1s[n * 68 + kp0 + 4];
                }
                #pragma unroll
                for (int mf = 0; mf < 2; mf++)
                    #pragma unroll
                    for (int nf = 0; nf < 8; nf++)
                        mma_f16(acc[mf][nf], aall[ks][mf], b[nf]);
            }

            // bias+relu -> f16 A-frags (register rename) -> layer-2 mma
            #pragma unroll
            for (int c = 0; c < 4; c++) {
                uint32_t amf[2][4];
                #pragma unroll
                for (int half = 0; half < 2; half++) {
                    int nf = 2 * c + half;
                    int col = qbase + 8 * nf + 2 * tg;
                    float2 bb1 = *(float2*)&b1s[col];
                    #pragma unroll
                    for (int mf = 0; mf < 2; mf++) {
                        float v0 = fmaxf(acc[mf][nf][0] + bb1.x, 0.f);
                        float v1 = fmaxf(acc[mf][nf][1] + bb1.y, 0.f);
                        float v2 = fmaxf(acc[mf][nf][2] + bb1.x, 0.f);
                        float v3 = fmaxf(acc[mf][nf][3] + bb1.y, 0.f);
                        amf[mf][2 * half]     = pack_h2(v0, v1);
                        amf[mf][2 * half + 1] = pack_h2(v2, v3);
                    }
                }
                const int cg = 4 * q0 + c;           // global 16-wide k-chunk
                uint32_t bb[2][2];
                #pragma unroll
                for (int nf2 = 0; nf2 < 2; nf2++) {
                    int n = nf2 * 8 + g;
                    bb[nf2][0] = W2s[n * 132 + 8 * cg + tg];
                    bb[nf2][1] = W2s[n * 132 + 8 * cg + tg + 4];
                }
                #pragma unroll
                for (int mf = 0; mf < 2; mf++)
                    #pragma unroll
                    for (int nf2 = 0; nf2 < 2; nf2++)
                        mma_f16(s2[mf][nf2], amf[mf], bb[nf2]);
            }
        }

        // ---- softmax + stores, all in registers (quad = one row's 16 cols) ----
        #pragma unroll
        for (int mf = 0; mf < 2; mf++) {
            #pragma unroll
            for (int rh = 0; rh < 2; rh++) {       // rh=0 -> row g, rh=1 -> row g+8
                float sv[4];
                sv[0] = s2[mf][0][2 * rh]     + b2s[2 * tg];
                sv[1] = s2[mf][0][2 * rh + 1] + b2s[2 * tg + 1];
                sv[2] = s2[mf][1][2 * rh]     + b2s[8 + 2 * tg];
                sv[3] = s2[mf][1][2 * rh + 1] + b2s[8 + 2 * tg + 1];

                float m = fmaxf(fmaxf(sv[0], sv[1]), fmaxf(sv[2], sv[3]));
                m = fmaxf(m, __shfl_xor_sync(0xFFFFFFFFu, m, 1));
                m = fmaxf(m, __shfl_xor_sync(0xFFFFFFFFu, m, 2));
                float ssum = 0.f;
                #pragma unroll
                for (int j = 0; j < 4; j++) { sv[j] = __expf(sv[j] - m); ssum += sv[j]; }
                ssum += __shfl_xor_sync(0xFFFFFFFFu, ssum, 1);
                ssum += __shfl_xor_sync(0xFFFFFFFFu, ssum, 2);
                float inv = 1.f / ssum;
                #pragma unroll
                for (int j = 0; j < 4; j++) sv[j] *= inv;

                int gr = row_base + rb + mf * 16 + g + 8 * rh;
                if (gr < N) {
                    *(float2*)&C[(size_t)gr * KCL + 2 * tg]     = make_float2(sv[0], sv[1]);
                    *(float2*)&C[(size_t)gr * KCL + 8 + 2 * tg] = make_float2(sv[2], sv[3]);
                    if (write_u8) {
                        uint16_t lo = (uint16_t)(__float2uint_rn(sv[0] * 255.f)
                                    | (__float2uint_rn(sv[1] * 255.f) << 8));
                        uint16_t hi = (uint16_t)(__float2uint_rn(sv[2] * 255.f)
                                    | (__float2uint_rn(sv[3] * 255.f) << 8));
                        uint16_t* row8 = (uint16_t*)&g_Cu8[gr];
                        row8[tg]     = lo;
                        row8[4 + tg] = hi;
                    }
                }
            }
        }
        // next tile's phase-0 STS is ordered by the post-aall __syncthreads
    }
}

__inline__ __device__ float warp_reduce_sum(float v) {
    #pragma unroll
    for (int o = 16; o > 0; o >>= 1)
        v += __shfl_xor_sync(0xFFFFFFFFu, v, o);
    return v;
}

__device__ __forceinline__ unsigned int u8x16_dot(uint4 a, uint4 b) {
    unsigned int s = 0u;
    s = __dp4a(a.x, b.x, s);
    s = __dp4a(a.y, b.y, s);
    s = __dp4a(a.z, b.z, s);
    s = __dp4a(a.w, b.w, s);
    return s;
}

// edge gather + reduce + (last block) finalize; dtype probe integrated (R12)
__global__ __launch_bounds__(256)
void edge_sum_kernel(const void* __restrict__ ei_raw,
                     const float* __restrict__ C,
                     int E, int N, int use_u8,
                     float* __restrict__ out, int nk, int do_write,
                     float inv_scale)
{
    const int tid = threadIdx.x;
    const int* ei32 = (const int*)ei_raw;
    int any = 0;
    #pragma unroll
    for (int s = 0; s < 2; s++) {
        long long j = ((long long)(tid * 2 + s) * E) >> 9;
        any |= ei32[2 * j + 1];
    }
    const int is64 = (__syncthreads_or(any) == 0);

    const int tid_g = blockIdx.x * blockDim.x + tid;
    const int total = gridDim.x * blockDim.x;
    float part = 0.f;

    if (use_u8) {
        const uint4* Cu = (const uint4*)g_Cu8;
        if (is64) {
            const long long* ei = (const long long*)ei_raw;
            for (int e = tid_g; e < E; e += total) {
                int u = (int)ei[e];
                int v = (int)ei[(size_t)E + e];
                u = ((unsigned)u < (unsigned)N) ? u : 0;
                v = ((unsigned)v < (unsigned)N) ? v : 0;
                uint4 a = __ldg(&Cu[u]);
                uint4 b = __ldg(&Cu[v]);
                part += (float)u8x16_dot(a, b);
            }
        } else {
            for (int e = tid_g; e < E; e += total) {
                int u = ei32[e];
                int v = ei32[(size_t)E + e];
                u = ((unsigned)u < (unsigned)N) ? u : 0;
                v = ((unsigned)v < (unsigned)N) ? v : 0;
                uint4 a = __ldg(&Cu[u]);
                uint4 b = __ldg(&Cu[v]);
                part += (float)u8x16_dot(a, b);
            }
        }
    } else {
        const int lane4 = tid_g & 3;
        const int q0 = tid_g >> 2;
        const int nq = total >> 2;
        const float4* C4 = (const float4*)C;
        if (is64) {
            const long long* ei = (const long long*)ei_raw;
            for (int e = q0; e < E; e += nq) {
                int u = (int)ei[e];
                int v = (int)ei[(size_t)E + e];
                u = ((unsigned)u < (unsigned)N) ? u : 0;
                v = ((unsigned)v < (unsigned)N) ? v : 0;
                float4 a = __ldg(&C4[(size_t)u * 4 + lane4]);
                float4 b = __ldg(&C4[(size_t)v * 4 + lane4]);
                part += a.x * b.x + a.y * b.y + a.z * b.z + a.w * b.w;
            }
        } else {
            for (int e = q0; e < E; e += nq) {
                int u = ei32[e];
                int v = ei32[(size_t)E + e];
                u = ((unsigned)u < (unsigned)N) ? u : 0;
                v = ((unsigned)v < (unsigned)N) ? v : 0;
                float4 a = __ldg(&C4[(size_t)u * 4 + lane4]);
                float4 b = __ldg(&C4[(size_t)v * 4 + lane4]);
                part += a.x * b.x + a.y * b.y + a.z * b.z + a.w * b.w;
            }
        }
    }

    part = warp_reduce_sum(part);
    __shared__ float ws[8];
    int lane = tid & 31, wrp = tid >> 5;
    if (lane == 0) ws[wrp] = part;
    __syncthreads();
    if (tid == 0) {
        float v = 0.f;
        #pragma unroll
        for (int w = 0; w < 8; w++) v += ws[w];
        atomicAdd(&g_edge_sum, v);
        __threadfence();
        int t = atomicAdd(&g_done, 1);
        if (t == gridDim.x - 1) {
            if (do_write) out[nk] = -g_edge_sum * inv_scale / (float)E;
            g_edge_sum = 0.f;
            g_done = 0;
        }
    }
}

extern "C" void kernel_launch(void* const* d_in, const int* in_sizes, int n_in,
                              void* d_out, int out_size)
{
    const float* x  = (const float*)d_in[0];
    const void*  ei = d_in[1];
    const float* W1 = (const float*)d_in[2];
    const float* b1 = (const float*)d_in[3];
    const float* W2 = (const float*)d_in[4];
    const float* b2 = (const float*)d_in[5];
    float* out = (float*)d_out;

    const int N = in_sizes[0] / D_IN;
    const int E = in_sizes[1] / 2;
    const int use_u8 = (N <= CB_CAP) ? 1 : 0;
    const int nk = N * KCL;
    const int ntiles = (N + TM - 1) / TM;
    const float inv_scale = use_u8 ? (1.0f / (255.0f * 255.0f)) : 1.0f;

    cudaFuncSetAttribute(fused_mlp_softmax,
                         cudaFuncAttributeMaxDynamicSharedMemorySize, SMEM_BYTES);

    int grid = 296;                      // 2 CTAs x 148 SMs, persistent
    if (grid > ntiles) grid = ntiles;
    fused_mlp_softmax<<<grid, NT, SMEM_BYTES>>>(x, W1, b1, W2, b2, out,
                                                N, ntiles, use_u8);

    edge_sum_kernel<<<1184, 256>>>(ei, out, E, N, use_u8,
                                   out, nk, out_size > nk ? 1 : 0, inv_scale);
}

// round 15
// speedup vs baseline: 1.0814x; 1.0814x over previous
#include <cuda_runtime.h>
#include <cuda_fp16.h>
#include <cstdint>

#define D_IN 128
#define D_H  256
#define KCL  16
#define TM   64
#define NT   256

// ---- smem layout (32-bit word offsets) ----
#define SM_XS  0                       // xs  [64][68]  fp16x2 kpairs
#define SM_W1  (64 * 68)               // W1h [256][68] fp16x2 (n-major, kpair cols)
#define SM_W2  (SM_W1 + 256 * 68)      // W2h [16][132] fp16x2
#define SM_B1  (SM_W2 + 16 * 132)      // b1  [256] fp32
#define SM_B2  (SM_B1 + 256)           // b2  [16]  fp32
#define SM_TOT (SM_B2 + 16)            // 24144 words
#define SMEM_BYTES (SM_TOT * 4)        // 96576 B -> 2 CTAs/SM

// overlays of the xs region (4352 words), used after phase 1
#define STGP 17
#define PP 66

#define CB_CAP 131072
__device__ uint4 g_Cu8[CB_CAP];        // u8 fixed-point copy of C, 16 B/row
__device__ float g_edge_sum;
__device__ int   g_done;

__device__ __forceinline__ uint32_t pack_h2(float a, float b) {
    __half2 h = __floats2half2_rn(a, b);
    return *(uint32_t*)&h;
}

__device__ __forceinline__ uint32_t smem_u32(const void* p) {
    uint32_t a;
    asm("{ .reg .u64 t; cvta.to.shared.u64 t, %1; cvt.u32.u64 %0, t; }" : "=r"(a) : "l"(p));
    return a;
}

#define LDSM_X4(r0, r1, r2, r3, addr) \
    asm volatile("ldmatrix.sync.aligned.m8n8.x4.shared.b16 {%0,%1,%2,%3}, [%4];" \
                 : "=r"(r0), "=r"(r1), "=r"(r2), "=r"(r3) : "r"(addr))

__device__ __forceinline__ void mma_f16(float* d, const uint32_t* a, const uint32_t* b) {
    asm volatile(
        "mma.sync.aligned.m16n8k16.row.col.f32.f16.f16.f32 "
        "{%0,%1,%2,%3}, {%4,%5,%6,%7}, {%8,%9}, {%0,%1,%2,%3};"
        : "+f"(d[0]), "+f"(d[1]), "+f"(d[2]), "+f"(d[3])
        : "r"(a[0]), "r"(a[1]), "r"(a[2]), "r"(a[3]), "r"(b[0]), "r"(b[1]));
}

__device__ __forceinline__ void load_x_regs(float4* xr, const float4* xv,
                                            int row_base, int N, int r0, int c4)
{
    #pragma unroll
    for (int k = 0; k < 8; k++) {
        int gr = row_base + r0 + 8 * k;
        if (gr < N) xr[k] = __ldg(&xv[(size_t)gr * 32 + c4]);
        else        xr[k] = make_float4(0.f, 0.f, 0.f, 0.f);
    }
}

// Persistent fused MLP+softmax; phase-1 operands via ldmatrix.x4.
__global__ __launch_bounds__(NT, 2)
void fused_mlp_softmax(const float* __restrict__ x,
                       const float* __restrict__ W1,
                       const float* __restrict__ b1,
                       const float* __restrict__ W2,
                       const float* __restrict__ b2,
                       float* __restrict__ C,
                       int N, int ntiles, int write_u8)
{
    extern __shared__ float smf[];
    uint32_t* smw = (uint32_t*)smf;
    uint32_t* xs  = smw + SM_XS;
    uint32_t* W1s = smw + SM_W1;
    uint32_t* W2s = smw + SM_W2;
    float* b1s = smf + SM_B1;
    float* b2s = smf + SM_B2;
    const uint32_t sb = smem_u32(smf);

    const int tid = threadIdx.x;
    const int wid = tid >> 5, lane = tid & 31;
    const int g = lane >> 2, tg = lane & 3;
    const int rw = wid >> 2, cw = wid & 3;
    const int rb = rw * 32, nb = cw * 64;

    const int xr0 = tid >> 5;
    const int xc4 = tid & 31;

    for (int i = tid; i < 256 * 64; i += NT) {
        int n = i & 255, kp = i >> 8;
        W1s[n * 68 + kp] = pack_h2(W1[(2 * kp) * D_H + n], W1[(2 * kp + 1) * D_H + n]);
    }
    for (int i = tid; i < 16 * 128; i += NT) {
        int kk = i & 15, kp = i >> 4;
        W2s[kk * 132 + kp] = pack_h2(W2[(2 * kp) * KCL + kk], W2[(2 * kp + 1) * KCL + kk]);
    }
    b1s[tid] = b1[tid];
    if (tid < KCL) b2s[tid] = b2[tid];

    // ---- loop-invariant ldmatrix lane addresses ----
    // A (per mf): m0 rows r0..+7 chunk, m1 rows +8 chunk, m2/m3 same rows chunk+16B
    uint32_t aaddr[2];
    {
        int row = rb + (lane & 15);
        int cofs = (lane & 16) ? 4 : 0;
        aaddr[0] = sb + 4 * ((SM_XS + (row)      * 68) + cofs);
        aaddr[1] = sb + 4 * ((SM_XS + (row + 16) * 68) + cofs);
    }
    // B (per nf-pair): m0/m1 rows n0..+7 chunk/(chunk+16B), m2/m3 rows +8
    uint32_t baddr[4];
    #pragma unroll
    for (int nfp = 0; nfp < 4; nfp++) {
        int row = nb + 16 * nfp + (lane & 7) + ((lane & 16) ? 8 : 0);
        int cofs = (lane & 8) ? 4 : 0;
        baddr[nfp] = sb + 4 * ((SM_W1 + row * 68) + cofs);
    }

    const float4* xv = (const float4*)x;
    float4 xr[8];
    int tile = blockIdx.x;
    if (tile < ntiles)
        load_x_regs(xr, xv, tile * TM, N, xr0, xc4);

    for (; tile < ntiles; tile += gridDim.x) {
        const int row_base = tile * TM;

        // ---- phase 0: registers -> fp16x2 smem ----
        #pragma unroll
        for (int k = 0; k < 8; k++) {
            int r = xr0 + 8 * k;
            uint2 u;
            u.x = pack_h2(xr[k].x, xr[k].y);
            u.y = pack_h2(xr[k].z, xr[k].w);
            *(uint2*)&xs[r * 68 + 2 * xc4] = u;
        }
        __syncthreads();

        // ---- phase 1: layer 1 fp16 mma via ldmatrix, warp tile 32x64 ----
        float acc[2][8][4];
        #pragma unroll
        for (int mf = 0; mf < 2; mf++)
            #pragma unroll
            for (int nf = 0; nf < 8; nf++)
                #pragma unroll
                for (int q = 0; q < 4; q++) acc[mf][nf][q] = 0.f;

        #pragma unroll
        for (int ks = 0; ks < 8; ks++) {
            const uint32_t kofs = 32u * ks;          // 8 kpairs = 32 bytes
            uint32_t a[2][4];
            LDSM_X4(a[0][0], a[0][1], a[0][2], a[0][3], aaddr[0] + kofs);
            LDSM_X4(a[1][0], a[1][1], a[1][2], a[1][3], aaddr[1] + kofs);
            uint32_t b[8][2];
            #pragma unroll
            for (int nfp = 0; nfp < 4; nfp++)
                LDSM_X4(b[2 * nfp][0], b[2 * nfp][1], b[2 * nfp + 1][0], b[2 * nfp + 1][1],
                        baddr[nfp] + kofs);
            #pragma unroll
            for (int mf = 0; mf < 2; mf++)
                #pragma unroll
                for (int nf = 0; nf < 8; nf++)
                    mma_f16(acc[mf][nf], a[mf], b[nf]);
        }
        __syncthreads();   // xs dead; reuse as stg

        // ---- phase 2+3 fused, two half-K passes through xs region ----
        float s2[2][2][4];
        #pragma unroll
        for (int mf = 0; mf < 2; mf++)
            #pragma unroll
            for (int nf2 = 0; nf2 < 2; nf2++)
                #pragma unroll
                for (int q = 0; q < 4; q++) s2[mf][nf2][q] = 0.f;

        uint32_t* stg = xs + wid * 544;

        // pass 0
        #pragma unroll
        for (int mf = 0; mf < 2; mf++) {
            #pragma unroll
            for (int nf = 0; nf < 4; nf++) {
                int col = nb + nf * 8 + 2 * tg;
                float bc0 = b1s[col], bc1 = b1s[col + 1];
                int row = mf * 16 + g;
                int kp = (4 * nf + tg) & 15;
                stg[row * STGP + kp] = pack_h2(fmaxf(acc[mf][nf][0] + bc0, 0.f),
                                               fmaxf(acc[mf][nf][1] + bc1, 0.f));
                stg[(row + 8) * STGP + kp] = pack_h2(fmaxf(acc[mf][nf][2] + bc0, 0.f),
                                                     fmaxf(acc[mf][nf][3] + bc1, 0.f));
            }
        }
        __syncwarp();
        {
            const int kbase = (nb >> 1);
            #pragma unroll
            for (int ks = 0; ks < 2; ks++) {
                const int kp0 = 8 * ks + tg;
                uint32_t bb[2][2];
                #pragma unroll
                for (int nf2 = 0; nf2 < 2; nf2++) {
                    int n = nf2 * 8 + g;
                    bb[nf2][0] = W2s[n * 132 + kbase + kp0];
                    bb[nf2][1] = W2s[n * 132 + kbase + kp0 + 4];
                }
                #pragma unroll
                for (int mf = 0; mf < 2; mf++) {
                    int r0 = mf * 16 + g;
                    uint32_t a[4];
                    a[0] = stg[r0 * STGP + kp0];
                    a[1] = stg[(r0 + 8) * STGP + kp0];
                    a[2] = stg[r0 * STGP + kp0 + 4];
                    a[3] = stg[(r0 + 8) * STGP + kp0 + 4];
                    #pragma unroll
                    for (int nf2 = 0; nf2 < 2; nf2++)
                        mma_f16(s2[mf][nf2], a, bb[nf2]);
                }
            }
        }
        __syncwarp();

        // pass 1
        #pragma unroll
        for (int mf = 0; mf < 2; mf++) {
            #pragma unroll
            for (int nf = 4; nf < 8; nf++) {
                int col = nb + nf * 8 + 2 * tg;
                float bc0 = b1s[col], bc1 = b1s[col + 1];
                int row = mf * 16 + g;
                int kp = (4 * nf + tg) & 15;
                stg[row * STGP + kp] = pack_h2(fmaxf(acc[mf][nf][0] + bc0, 0.f),
                                               fmaxf(acc[mf][nf][1] + bc1, 0.f));
                stg[(row + 8) * STGP + kp] = pack_h2(fmaxf(acc[mf][nf][2] + bc0, 0.f),
                                                     fmaxf(acc[mf][nf][3] + bc1, 0.f));
            }
        }
        __syncwarp();

        // acc dead: prefetch next tile's x
        {
            int nt2 = tile + gridDim.x;
            if (nt2 < ntiles)
                load_x_regs(xr, xv, nt2 * TM, N, xr0, xc4);
        }

        {
            const int kbase = (nb >> 1) + 16;
            #pragma unroll
            for (int ks = 0; ks < 2; ks++) {
                const int kp0 = 8 * ks + tg;
                uint32_t bb[2][2];
                #pragma unroll
                for (int nf2 = 0; nf2 < 2; nf2++) {
                    int n = nf2 * 8 + g;
                    bb[nf2][0] = W2s[n * 132 + kbase + kp0];
                    bb[nf2][1] = W2s[n * 132 + kbase + kp0 + 4];
                }
                #pragma unroll
                for (int mf = 0; mf < 2; mf++) {
                    int r0 = mf * 16 + g;
                    uint32_t a[4];
                    a[0] = stg[r0 * STGP + kp0];
                    a[1] = stg[(r0 + 8) * STGP + kp0];
                    a[2] = stg[r0 * STGP + kp0 + 4];
                    a[3] = stg[(r0 + 8) * STGP + kp0 + 4];
                    #pragma unroll
                    for (int nf2 = 0; nf2 < 2; nf2++)
                        mma_f16(s2[mf][nf2], a, bb[nf2]);
                }
            }
        }
        __syncthreads();   // stg dead; reuse xs region as P

        // ---- phase 4: K-partials ----
        float* P = (float*)xs;
        #pragma unroll
        for (int mf = 0; mf < 2; mf++) {
            #pragma unroll
            for (int nf2 = 0; nf2 < 2; nf2++) {
                int row = rb + mf * 16 + g;
                int kk0 = nf2 * 8 + 2 * tg;
                *(float2*)&P[row * PP + cw * 16 + kk0] =
                    make_float2(s2[mf][nf2][0], s2[mf][nf2][1]);
                *(float2*)&P[(row + 8) * PP + cw * 16 + kk0] =
                    make_float2(s2[mf][nf2][2], s2[mf][nf2][3]);
            }
        }
        __syncthreads();

        // ---- phase 5: reduce, softmax, stores (fp32 C + u8 copy) ----
        {
            const int row = tid >> 2;
            const int q   = tid & 3;
            const int kb  = 4 * q;

            float sv[4];
            #pragma unroll
            for (int j = 0; j < 4; j++) sv[j] = b2s[kb + j];
            #pragma unroll
            for (int c = 0; c < 4; c++) {
                float2 pA = *(float2*)&P[row * PP + 16 * c + kb];
                float2 pB = *(float2*)&P[row * PP + 16 * c + kb + 2];
                sv[0] += pA.x; sv[1] += pA.y; sv[2] += pB.x; sv[3] += pB.y;
            }
            float m = fmaxf(fmaxf(sv[0], sv[1]), fmaxf(sv[2], sv[3]));
            m = fmaxf(m, __shfl_xor_sync(0xFFFFFFFFu, m, 1, 4));
            m = fmaxf(m, __shfl_xor_sync(0xFFFFFFFFu, m, 2, 4));
            float ssum = 0.f;
            #pragma unroll
            for (int j = 0; j < 4; j++) { sv[j] = __expf(sv[j] - m); ssum += sv[j]; }
            ssum += __shfl_xor_sync(0xFFFFFFFFu, ssum, 1, 4);
            ssum += __shfl_xor_sync(0xFFFFFFFFu, ssum, 2, 4);
            float inv = 1.f / ssum;
            #pragma unroll
            for (int j = 0; j < 4; j++) sv[j] *= inv;

            int gr = row_base + row;
            if (gr < N) {
                *(float4*)&C[(size_t)gr * KCL + kb] =
                    make_float4(sv[0], sv[1], sv[2], sv[3]);
                if (write_u8) {
                    uint32_t v0 = __float2uint_rn(sv[0] * 255.f);
                    uint32_t v1 = __float2uint_rn(sv[1] * 255.f);
                    uint32_t v2 = __float2uint_rn(sv[2] * 255.f);
                    uint32_t v3 = __float2uint_rn(sv[3] * 255.f);
                    ((uint32_t*)g_Cu8)[(size_t)gr * 4 + q] =
                        v0 | (v1 << 8) | (v2 << 16) | (v3 << 24);
                }
            }
        }
        __syncthreads();
    }
}

__inline__ __device__ float warp_reduce_sum(float v) {
    #pragma unroll
    for (int o = 16; o > 0; o >>= 1)
        v += __shfl_xor_sync(0xFFFFFFFFu, v, o);
    return v;
}

__device__ __forceinline__ unsigned int u8x16_dot(uint4 a, uint4 b) {
    unsigned int s = 0u;
    s = __dp4a(a.x, b.x, s);
    s = __dp4a(a.y, b.y, s);
    s = __dp4a(a.z, b.z, s);
    s = __dp4a(a.w, b.w, s);
    return s;
}

// edge gather + reduce + (last block) finalize; dtype probe integrated (R12)
__global__ __launch_bounds__(256)
void edge_sum_kernel(const void* __restrict__ ei_raw,
                     const float* __restrict__ C,
                     int E, int N, int use_u8,
                     float* __restrict__ out, int nk, int do_write,
                     float inv_scale)
{
    const int tid = threadIdx.x;
    const int* ei32 = (const int*)ei_raw;
    int any = 0;
    #pragma unroll
    for (int s = 0; s < 2; s++) {
        long long j = ((long long)(tid * 2 + s) * E) >> 9;
        any |= ei32[2 * j + 1];
    }
    const int is64 = (__syncthreads_or(any) == 0);

    const int tid_g = blockIdx.x * blockDim.x + tid;
    const int total = gridDim.x * blockDim.x;
    float part = 0.f;

    if (use_u8) {
        const uint4* Cu = (const uint4*)g_Cu8;
        if (is64) {
            const long long* ei = (const long long*)ei_raw;
            for (int e = tid_g; e < E; e += total) {
                int u = (int)ei[e];
                int v = (int)ei[(size_t)E + e];
                u = ((unsigned)u < (unsigned)N) ? u : 0;
                v = ((unsigned)v < (unsigned)N) ? v : 0;
                uint4 a = __ldg(&Cu[u]);
                uint4 b = __ldg(&Cu[v]);
                part += (float)u8x16_dot(a, b);
            }
        } else {
            for (int e = tid_g; e < E; e += total) {
                int u = ei32[e];
                int v = ei32[(size_t)E + e];
                u = ((unsigned)u < (unsigned)N) ? u : 0;
                v = ((unsigned)v < (unsigned)N) ? v : 0;
                uint4 a = __ldg(&Cu[u]);
                uint4 b = __ldg(&Cu[v]);
                part += (float)u8x16_dot(a, b);
            }
        }
    } else {
        const int lane4 = tid_g & 3;
        const int q0 = tid_g >> 2;
        const int nq = total >> 2;
        const float4* C4 = (const float4*)C;
        if (is64) {
            const long long* ei = (const long long*)ei_raw;
            for (int e = q0; e < E; e += nq) {
                int u = (int)ei[e];
                int v = (int)ei[(size_t)E + e];
                u = ((unsigned)u < (unsigned)N) ? u : 0;
                v = ((unsigned)v < (unsigned)N) ? v : 0;
                float4 a = __ldg(&C4[(size_t)u * 4 + lane4]);
                float4 b = __ldg(&C4[(size_t)v * 4 + lane4]);
                part += a.x * b.x + a.y * b.y + a.z * b.z + a.w * b.w;
            }
        } else {
            for (int e = q0; e < E; e += nq) {
                int u = ei32[e];
                int v = ei32[(size_t)E + e];
                u = ((unsigned)u < (unsigned)N) ? u : 0;
                v = ((unsigned)v < (unsigned)N) ? v : 0;
                float4 a = __ldg(&C4[(size_t)u * 4 + lane4]);
                float4 b = __ldg(&C4[(size_t)v * 4 + lane4]);
                part += a.x * b.x + a.y * b.y + a.z * b.z + a.w * b.w;
            }
        }
    }

    part = warp_reduce_sum(part);
    __shared__ float ws[8];
    int lane = tid & 31, wrp = tid >> 5;
    if (lane == 0) ws[wrp] = part;
    __syncthreads();
    if (tid == 0) {
        float v = 0.f;
        #pragma unroll
        for (int w = 0; w < 8; w++) v += ws[w];
        atomicAdd(&g_edge_sum, v);
        __threadfence();
        int t = atomicAdd(&g_done, 1);
        if (t == gridDim.x - 1) {
            if (do_write) out[nk] = -g_edge_sum * inv_scale / (float)E;
            g_edge_sum = 0.f;
            g_done = 0;
        }
    }
}

extern "C" void kernel_launch(void* const* d_in, const int* in_sizes, int n_in,
                              void* d_out, int out_size)
{
    const float* x  = (const float*)d_in[0];
    const void*  ei = d_in[1];
    const float* W1 = (const float*)d_in[2];
    const float* b1 = (const float*)d_in[3];
    const float* W2 = (const float*)d_in[4];
    const float* b2 = (const float*)d_in[5];
    float* out = (float*)d_out;

    const int N = in_sizes[0] / D_IN;
    const int E = in_sizes[1] / 2;
    const int use_u8 = (N <= CB_CAP) ? 1 : 0;
    const int nk = N * KCL;
    const int ntiles = (N + TM - 1) / TM;
    const float inv_scale = use_u8 ? (1.0f / (255.0f * 255.0f)) : 1.0f;

    cudaFuncSetAttribute(fused_mlp_softmax,
                         cudaFuncAttributeMaxDynamicSharedMemorySize, SMEM_BYTES);

    int grid = 296;                      // 2 CTAs x 148 SMs, persistent
    if (grid > ntiles) grid = ntiles;
    fused_mlp_softmax<<<grid, NT, SMEM_BYTES>>>(x, W1, b1, W2, b2, out,
                                                N, ntiles, use_u8);

    edge_sum_kernel<<<1184, 256>>>(ei, out, E, N, use_u8,
                                   out, nk, out_size > nk ? 1 : 0, inv_scale);
}